// round 1
// baseline (speedup 1.0000x reference)
#include <cuda_runtime.h>

#define TT      2048
#define BB      4096
#define NH1     9
#define NH2     32
#define NDIN    5
#define OUTLEN  25
#define TASKS_PER_WARP 10          // 10 triples of lanes, lanes 30,31 idle
#define WARPS_PER_DIR  410         // ceil(4096/10)

// Scratch: concat [h_f(9), h_b(9)] per batch element
__device__ float g_y[BB * 2 * NH1];

__device__ __forceinline__ float ftanh(float x) {
    // tanh(x) = (e^{2x}-1)/(e^{2x}+1); clamp so e^{2x} stays finite.
    x = fminf(fmaxf(x, -9.0f), 9.0f);
    float e = __expf(2.0f * x);
    return __fdividef(e - 1.0f, e + 1.0f);
}

// ---------------------------------------------------------------------------
// Stage 1: bidirectional Elman RNN, H1=9, over T=2048.
// One (batch, direction) task = 3 consecutive lanes; lane r owns hidden units
// 3r..3r+2. h exchanged with 9 shfls per step. Warps 0..409 are forward,
// 410..819 backward (direction is warp-uniform -> no divergence).
// x is read in aligned 4-step groups of 5 float4 loads, double buffered.
// ---------------------------------------------------------------------------
__global__ __launch_bounds__(128) void rnn1_kernel(
    const float* __restrict__ x,
    const float* __restrict__ wih_f, const float* __restrict__ whh_f,
    const float* __restrict__ bih_f, const float* __restrict__ bhh_f,
    const float* __restrict__ wih_b, const float* __restrict__ whh_b,
    const float* __restrict__ bih_b, const float* __restrict__ bhh_b)
{
    const int warp = blockIdx.x * (blockDim.x >> 5) + (threadIdx.x >> 5);
    const int lane = threadIdx.x & 31;
    const int tri  = lane / 3;          // 0..10 (10 -> idle lanes 30,31)
    const int r    = lane - tri * 3;    // 0..2

    const bool bwd = (warp >= WARPS_PER_DIR);
    const int  wg  = bwd ? (warp - WARPS_PER_DIR) : warp;
    int b = wg * TASKS_PER_WARP + tri;
    const bool valid = (tri < TASKS_PER_WARP) && (b < BB);
    const int  bc = min(b, BB - 1);     // clamped for safe loads on idle lanes

    const float* wih = bwd ? wih_b : wih_f;
    const float* whh = bwd ? whh_b : whh_f;
    const float* bih = bwd ? bih_b : bih_f;
    const float* bhh = bwd ? bhh_b : bhh_f;

    // Per-lane weight rows (units 3r..3r+2)
    float Wi[3][5], Wh[3][9], bbv[3];
    #pragma unroll
    for (int m = 0; m < 3; m++) {
        const int j = 3 * r + m;
        #pragma unroll
        for (int k = 0; k < 5; k++) Wi[m][k] = wih[j * 5 + k];
        #pragma unroll
        for (int i = 0; i < 9; i++) Wh[m][i] = whh[j * 9 + i];
        bbv[m] = bih[j] + bhh[j];
    }

    const float* xbase = x + (size_t)bc * (TT * NDIN);
    const int base = tri * 3;          // first lane of this triple

    float H[9];
    #pragma unroll
    for (int i = 0; i < 9; i++) H[i] = 0.0f;
    float h0 = 0.0f, h1 = 0.0f, h2 = 0.0f;

    float xb[20], xn[20];

    // Load one 4-step group (20 floats = 5 aligned float4s).
    auto LOADG = [&](int g, float* dst) {
        const int t0 = bwd ? (TT - 4 - 4 * g) : (4 * g);
        const float4* p = reinterpret_cast<const float4*>(xbase + t0 * NDIN);
        float4 v0 = p[0], v1 = p[1], v2 = p[2], v3 = p[3], v4 = p[4];
        dst[0]  = v0.x; dst[1]  = v0.y; dst[2]  = v0.z; dst[3]  = v0.w;
        dst[4]  = v1.x; dst[5]  = v1.y; dst[6]  = v1.z; dst[7]  = v1.w;
        dst[8]  = v2.x; dst[9]  = v2.y; dst[10] = v2.z; dst[11] = v2.w;
        dst[12] = v3.x; dst[13] = v3.y; dst[14] = v3.z; dst[15] = v3.w;
        dst[16] = v4.x; dst[17] = v4.y; dst[18] = v4.z; dst[19] = v4.w;
    };

    auto STEP = [&](float x0, float x1, float x2, float x3, float x4) {
        float a0, a1, a2;
        {
            float z = bbv[0];
            z = fmaf(Wi[0][0], x0, z); z = fmaf(Wi[0][1], x1, z);
            z = fmaf(Wi[0][2], x2, z); z = fmaf(Wi[0][3], x3, z);
            z = fmaf(Wi[0][4], x4, z);
            #pragma unroll
            for (int i = 0; i < 9; i++) z = fmaf(Wh[0][i], H[i], z);
            a0 = z;
        }
        {
            float z = bbv[1];
            z = fmaf(Wi[1][0], x0, z); z = fmaf(Wi[1][1], x1, z);
            z = fmaf(Wi[1][2], x2, z); z = fmaf(Wi[1][3], x3, z);
            z = fmaf(Wi[1][4], x4, z);
            #pragma unroll
            for (int i = 0; i < 9; i++) z = fmaf(Wh[1][i], H[i], z);
            a1 = z;
        }
        {
            float z = bbv[2];
            z = fmaf(Wi[2][0], x0, z); z = fmaf(Wi[2][1], x1, z);
            z = fmaf(Wi[2][2], x2, z); z = fmaf(Wi[2][3], x3, z);
            z = fmaf(Wi[2][4], x4, z);
            #pragma unroll
            for (int i = 0; i < 9; i++) z = fmaf(Wh[2][i], H[i], z);
            a2 = z;
        }
        h0 = ftanh(a0);
        h1 = ftanh(a1);
        h2 = ftanh(a2);
        // Exchange: H[3s+m] = unit (3s+m) from lane base+s
        #pragma unroll
        for (int s = 0; s < 3; s++) {
            H[3 * s + 0] = __shfl_sync(0xffffffffu, h0, base + s);
            H[3 * s + 1] = __shfl_sync(0xffffffffu, h1, base + s);
            H[3 * s + 2] = __shfl_sync(0xffffffffu, h2, base + s);
        }
    };

    LOADG(0, xb);
    const int NG = TT / 4;  // 512
    for (int g = 0; g < NG; g++) {
        if (g + 1 < NG) LOADG(g + 1, xn);
        if (!bwd) {
            STEP(xb[0],  xb[1],  xb[2],  xb[3],  xb[4]);
            STEP(xb[5],  xb[6],  xb[7],  xb[8],  xb[9]);
            STEP(xb[10], xb[11], xb[12], xb[13], xb[14]);
            STEP(xb[15], xb[16], xb[17], xb[18], xb[19]);
        } else {
            STEP(xb[15], xb[16], xb[17], xb[18], xb[19]);
            STEP(xb[10], xb[11], xb[12], xb[13], xb[14]);
            STEP(xb[5],  xb[6],  xb[7],  xb[8],  xb[9]);
            STEP(xb[0],  xb[1],  xb[2],  xb[3],  xb[4]);
        }
        #pragma unroll
        for (int i = 0; i < 20; i++) xb[i] = xn[i];
    }

    if (valid) {
        float* dst = g_y + b * (2 * NH1) + (bwd ? NH1 : 0) + 3 * r;
        dst[0] = h0; dst[1] = h1; dst[2] = h2;
    }
}

// ---------------------------------------------------------------------------
// Stage 2: H2=32 RNN for 25 steps (input only at t=0) + linear 32->3.
// One warp per batch element, lane j owns hidden unit j. Recurrence via
// 32-way shfl broadcast; output via 3 butterfly reductions per step.
// ---------------------------------------------------------------------------
__global__ __launch_bounds__(256) void rnn2_kernel(
    const float* __restrict__ wih2, const float* __restrict__ whh2,
    const float* __restrict__ bih2, const float* __restrict__ bhh2,
    const float* __restrict__ wout, const float* __restrict__ bout,
    float* __restrict__ out)
{
    const int warp = blockIdx.x * (blockDim.x >> 5) + (threadIdx.x >> 5);
    const int j = threadIdx.x & 31;
    if (warp >= BB) return;
    const int b = warp;

    float Wh[32], Wi[18];
    #pragma unroll
    for (int i = 0; i < 32; i++) Wh[i] = whh2[j * 32 + i];
    #pragma unroll
    for (int k = 0; k < 18; k++) Wi[k] = wih2[j * 18 + k];
    const float bj = bih2[j] + bhh2[j];
    const float Wo0 = wout[0 * 32 + j];
    const float Wo1 = wout[1 * 32 + j];
    const float Wo2 = wout[2 * 32 + j];
    const float bo0 = bout[0], bo1 = bout[1], bo2 = bout[2];

    // t = 0: h = tanh(Wih2 @ y + b)   (h_prev = 0)
    const float* y = g_y + (size_t)b * (2 * NH1);
    float z = bj;
    #pragma unroll
    for (int k = 0; k < 18; k++) z = fmaf(Wi[k], y[k], z);
    float h = ftanh(z);

    float* outp = out + (size_t)b * (OUTLEN * 3);

    auto EMIT = [&](int t) {
        float p0 = Wo0 * h, p1 = Wo1 * h, p2 = Wo2 * h;
        #pragma unroll
        for (int off = 16; off > 0; off >>= 1) {
            p0 += __shfl_xor_sync(0xffffffffu, p0, off);
            p1 += __shfl_xor_sync(0xffffffffu, p1, off);
            p2 += __shfl_xor_sync(0xffffffffu, p2, off);
        }
        if (j == 0) {
            outp[t * 3 + 0] = p0 + bo0;
            outp[t * 3 + 1] = p1 + bo1;
            outp[t * 3 + 2] = p2 + bo2;
        }
    };

    EMIT(0);
    for (int t = 1; t < OUTLEN; t++) {
        float acc = bj;
        #pragma unroll
        for (int i = 0; i < 32; i++)
            acc = fmaf(Wh[i], __shfl_sync(0xffffffffu, h, i), acc);
        h = ftanh(acc);
        EMIT(t);
    }
}

// ---------------------------------------------------------------------------
extern "C" void kernel_launch(void* const* d_in, const int* in_sizes, int n_in,
                              void* d_out, int out_size)
{
    const float* x      = (const float*)d_in[0];
    const float* wih_f  = (const float*)d_in[1];
    const float* whh_f  = (const float*)d_in[2];
    const float* bih_f  = (const float*)d_in[3];
    const float* bhh_f  = (const float*)d_in[4];
    const float* wih_b  = (const float*)d_in[5];
    const float* whh_b  = (const float*)d_in[6];
    const float* bih_b  = (const float*)d_in[7];
    const float* bhh_b  = (const float*)d_in[8];
    const float* wih2   = (const float*)d_in[9];
    const float* whh2   = (const float*)d_in[10];
    const float* bih2   = (const float*)d_in[11];
    const float* bhh2   = (const float*)d_in[12];
    const float* wout   = (const float*)d_in[13];
    const float* bout   = (const float*)d_in[14];
    float* out = (float*)d_out;

    // 820 warps total = 205 CTAs x 4 warps (410 fwd + 410 bwd)
    rnn1_kernel<<<205, 128>>>(x, wih_f, whh_f, bih_f, bhh_f,
                              wih_b, whh_b, bih_b, bhh_b);
    // 4096 warps = 512 CTAs x 8 warps
    rnn2_kernel<<<512, 256>>>(wih2, whh2, bih2, bhh2, wout, bout, out);
}